// round 16
// baseline (speedup 1.0000x reference)
#include <cuda_runtime.h>
#include <cuda_bf16.h>
#include <cstdint>

// Problem constants
#define Bsz  8
#define Tsz  256
#define Osz  16
#define Dsz  512
#define Hsz  8
#define HDsz 64
#define Mrows (Bsz*Tsz*Osz)      // 32768
#define ELEMS (Mrows*Dsz)        // 16777216
#define WSEG  (Dsz*Dsz)          // 262144
#define NGRP  (Bsz*Osz)          // 128
#define NDET  16

// ---------------------------------------------------------------------------
// Scratch (device globals: no allocation, graph-safe)
// ---------------------------------------------------------------------------
__device__ float g_out[ELEMS];                     // compact rows
__device__ float g_mask[Mrows];
__device__ int   g_bytespart[NDET];                // per-block detection partials
__device__ int   g_cnt[NGRP];
__device__ int   g_gstart[NGRP];
__device__ int   g_Mc;
__device__ int   g_tlist[NGRP*Tsz];
__device__ int   g_rowsrc[Mrows];                  // compact r -> X row index
__device__ int   g_rowbos[Mrows];                  // compact r -> (g<<8)|slot
__device__ int   g_rinv[Mrows];                    // X row -> compact r (valid rows only)
__device__ __align__(16) __nv_bfloat16 g_xhi[ELEMS];   // X split (COMPACT rows)
__device__ __align__(16) __nv_bfloat16 g_xlo[ELEMS];
__device__ __align__(16) __nv_bfloat16 g_ahi[ELEMS];   // att split (compact rows)
__device__ __align__(16) __nv_bfloat16 g_alo[ELEMS];
__device__ __align__(16) __nv_bfloat16 g_whi[4*WSEG];  // Wq,Wk,Wv,Wo split [k][n]
__device__ __align__(16) __nv_bfloat16 g_wlo[4*WSEG];
__device__ __align__(16) __nv_bfloat16 g_qhi[ELEMS];   // (g,h,slot,hd), pre-scaled
__device__ __align__(16) __nv_bfloat16 g_qlo[ELEMS];
__device__ __align__(16) __nv_bfloat16 g_khi[ELEMS];
__device__ __align__(16) __nv_bfloat16 g_klo[ELEMS];
__device__ __align__(16) __nv_bfloat16 g_vhi[ELEMS];
__device__ __align__(16) __nv_bfloat16 g_vlo[ELEMS];

// ---------------------------------------------------------------------------
// PTX helpers
// ---------------------------------------------------------------------------
__device__ __forceinline__ void cp16(uint32_t dst, const void* src) {
    asm volatile("cp.async.cg.shared.global [%0], [%1], 16;" :: "r"(dst), "l"(src));
}
__device__ __forceinline__ void st16z(uint32_t dst) {
    asm volatile("st.shared.v4.u32 [%0], {%1,%1,%1,%1};" :: "r"(dst), "r"(0u));
}
__device__ __forceinline__ void ldsm4(unsigned (&r)[4], uint32_t addr) {
    asm volatile("ldmatrix.sync.aligned.m8n8.x4.shared.b16 {%0,%1,%2,%3}, [%4];"
                 : "=r"(r[0]), "=r"(r[1]), "=r"(r[2]), "=r"(r[3]) : "r"(addr));
}
__device__ __forceinline__ void ldsm4t(unsigned (&r)[4], uint32_t addr) {
    asm volatile("ldmatrix.sync.aligned.m8n8.x4.trans.shared.b16 {%0,%1,%2,%3}, [%4];"
                 : "=r"(r[0]), "=r"(r[1]), "=r"(r[2]), "=r"(r[3]) : "r"(addr));
}
__device__ __forceinline__ void mma_bf16(float (&d)[4], const unsigned (&a)[4], unsigned b0, unsigned b1) {
    asm volatile("mma.sync.aligned.m16n8k16.row.col.f32.bf16.bf16.f32 "
                 "{%0,%1,%2,%3}, {%4,%5,%6,%7}, {%8,%9}, {%0,%1,%2,%3};"
                 : "+f"(d[0]), "+f"(d[1]), "+f"(d[2]), "+f"(d[3])
                 : "r"(a[0]), "r"(a[1]), "r"(a[2]), "r"(a[3]), "r"(b0), "r"(b1));
}
__device__ __forceinline__ unsigned packbf(float a, float b) {
    __nv_bfloat162 h = __floats2bfloat162_rn(a, b);
    return *(unsigned*)&h;
}

// ---------------------------------------------------------------------------
// Mask format detection over first 8192 int32 words (in-bounds for both
// possible marshalings; covers all bytes if byte-packed). Parallel, no atomics.
// ---------------------------------------------------------------------------
__global__ void detect_k(const unsigned int* __restrict__ mi)
{
    __shared__ int flag;
    if (threadIdx.x == 0) flag = 0;
    __syncthreads();
    int i = blockIdx.x * blockDim.x + threadIdx.x;   // 16 * 512 = 8192
    if (mi[i] > 1u) flag = 1;                        // benign race, same value
    __syncthreads();
    if (threadIdx.x == 0) g_bytespart[blockIdx.x] = flag;
}

// per-(b,o) compaction: normalize mask (writes g_mask) + counts + slot->t list
__global__ void comp_scan_k(const void* __restrict__ mraw)
{
    const int g = blockIdx.x, b = g >> 4, o = g & 15;
    const int tid = threadIdx.x, lane = tid & 31, w = tid >> 5;
    __shared__ int wtot[8];
    __shared__ int sbytes;
    if (tid < 32) {
        int f = (tid < NDET) ? g_bytespart[tid] : 0;
        #pragma unroll
        for (int off = 16; off > 0; off >>= 1) f |= __shfl_down_sync(0xffffffffu, f, off);
        if (tid == 0) sbytes = f;
    }
    __syncthreads();
    const bool bytes = (sbytes != 0);
    const size_t idx = (size_t)(b * Tsz + tid) * Osz + o;
    int v;
    if (bytes) v = ((const unsigned char*)mraw)[idx] ? 1 : 0;
    else       v = ((const unsigned int*)mraw)[idx] ? 1 : 0;
    g_mask[idx] = (float)v;

    unsigned bal = __ballot_sync(0xffffffffu, v);
    int pfx = __popc(bal & ((1u << lane) - 1u));
    if (lane == 31) wtot[w] = pfx + v;
    __syncthreads();
    int woff = 0;
    #pragma unroll
    for (int i = 0; i < 8; i++) woff += (i < w) ? wtot[i] : 0;
    if (v) g_tlist[g * Tsz + woff + pfx] = tid;
    if (tid == 255) g_cnt[g] = woff + pfx + v;
}

// compact row maps (forward + inverse) with fused per-block prefix over counts
__global__ void rowmap_k()
{
    __shared__ int scnt[NGRP];
    __shared__ int sgstart;
    const int g = blockIdx.x, s = threadIdx.x;
    if (s < NGRP) scnt[s] = g_cnt[s];
    __syncthreads();
    if (s == 0) {
        int acc = 0;
        for (int i = 0; i < g; i++) acc += scnt[i];
        sgstart = acc;
        g_gstart[g] = acc;
        if (g == NGRP - 1) g_Mc = acc + scnt[g];
    }
    __syncthreads();
    if (s < scnt[g]) {
        int t = g_tlist[g * Tsz + s];
        int r = sgstart + s;
        int xrow = (g >> 4) * (Tsz * Osz) + t * Osz + (g & 15);
        g_rowsrc[r] = xrow;
        g_rowbos[r] = (g << 8) | s;
        g_rinv[xrow] = r;
    }
}

// ---------------------------------------------------------------------------
// fp32 -> bf16 hi/lo split conversions
// ---------------------------------------------------------------------------
__device__ __forceinline__ void split4(float4 v, uint2& hi, uint2& lo) {
    __nv_bfloat162 h0 = __floats2bfloat162_rn(v.x, v.y);
    __nv_bfloat162 h1 = __floats2bfloat162_rn(v.z, v.w);
    float2 f0 = __bfloat1622float2(h0);
    float2 f1 = __bfloat1622float2(h1);
    __nv_bfloat162 l0 = __floats2bfloat162_rn(v.x - f0.x, v.y - f0.y);
    __nv_bfloat162 l1 = __floats2bfloat162_rn(v.z - f1.x, v.w - f1.y);
    hi.x = *(unsigned*)&h0; hi.y = *(unsigned*)&h1;
    lo.x = *(unsigned*)&l0; lo.y = *(unsigned*)&l1;
}

// fused conversions, 4 float4 per thread (MLP=4):
// blocks [0, 4096) = X gather-convert (compact rows),
// blocks [4096, 4352) = W split (4 matrices x 64 blocks).
#define XBLKS ((Mrows * 128) / 1024)    // 4096
__global__ void conv_k(const float4* __restrict__ x,
                       const float4* __restrict__ w0, const float4* __restrict__ w1,
                       const float4* __restrict__ w2, const float4* __restrict__ w3)
{
    const int blk = blockIdx.x;
    if (blk < XBLKS) {
        const int Mc = g_Mc;
        #pragma unroll
        for (int j = 0; j < 4; j++) {
            int i = blk * 1024 + j * 256 + threadIdx.x;   // compact float4 index
            int r = i >> 7;
            if (r >= Mc) continue;
            int xrow = g_rowsrc[r];
            uint2 hi, lo;
            split4(x[(size_t)xrow * 128 + (i & 127)], hi, lo);
            ((uint2*)g_xhi)[i] = hi;
            ((uint2*)g_xlo)[i] = lo;
        }
    } else {
        int wb = blk - XBLKS;                   // 0..255
        int mtx = wb >> 6;                      // 0..3
        const float4* src = (mtx == 0) ? w0 : (mtx == 1) ? w1 : (mtx == 2) ? w2 : w3;
        #pragma unroll
        for (int j = 0; j < 4; j++) {
            int i = (wb & 63) * 1024 + j * 256 + threadIdx.x; // 0..65535
            uint2 hi, lo;
            split4(src[i], hi, lo);
            size_t off = (size_t)mtx * (WSEG / 4) + i;
            ((uint2*)g_whi)[off] = hi;
            ((uint2*)g_wlo)[off] = lo;
        }
    }
}

// ---------------------------------------------------------------------------
// Tensor-core GEMM on COMPACT rows (split-bf16, 3-stage cp.async pipeline).
// MODE 0: fused QKV (blockIdx.z selects matrix); A = compact X splits,
//         C scattered to (g,h,slot) head-major bf16 hi/lo (Q scaled 0.125).
// MODE 3: A = compact att rows, C = compact g_out fp32.
// ---------------------------------------------------------------------------
#define A_STRIDE 40
#define B_STRIDE 136
#define A_BYTES  (128*A_STRIDE*2)          // 10240
#define B_BYTES  (32*B_STRIDE*2)           // 8704
#define STG_BYTES (2*A_BYTES + 2*B_BYTES)  // 37888
#define SMEM_TOTAL (3*STG_BYTES)           // 113664

template<int MODE>
__global__ __launch_bounds__(256, 2)
void bgemm_k(const float* __restrict__ bias0,
             const float* __restrict__ bias1,
             const float* __restrict__ bias2)
{
    const int Mc = g_Mc;
    const int m0 = blockIdx.y * 128;
    if (m0 >= Mc) return;

    const int z = (MODE == 0) ? blockIdx.z : 3;
    const __nv_bfloat16* Ahi = (MODE == 0) ? g_xhi : g_ahi;
    const __nv_bfloat16* Alo = (MODE == 0) ? g_xlo : g_alo;
    const __nv_bfloat16* Bhi = g_whi + (size_t)z * WSEG;
    const __nv_bfloat16* Blo = g_wlo + (size_t)z * WSEG;
    __nv_bfloat16* Chi = (z == 0) ? g_qhi : (z == 1) ? g_khi : g_vhi;
    __nv_bfloat16* Clo = (z == 0) ? g_qlo : (z == 1) ? g_klo : g_vlo;
    const float* bias = (MODE != 0) ? bias0 : (z == 0) ? bias0 : (z == 1) ? bias1 : bias2;
    const float scl = (MODE == 0 && z == 0) ? 0.125f : 1.f;

    extern __shared__ char smem[];
    const uint32_t sbase = (uint32_t)__cvta_generic_to_shared(smem);

    const int tid = threadIdx.x;
    const int lane = tid & 31;
    const int wid = tid >> 5;
    const int wm = wid & 3;
    const int wn = wid >> 2;
    const int n0 = blockIdx.x * 128;

    float acc[2][8][4];
    #pragma unroll
    for (int a = 0; a < 2; a++)
        #pragma unroll
        for (int b = 0; b < 8; b++)
            #pragma unroll
            for (int c = 0; c < 4; c++) acc[a][b][c] = 0.f;

    const int aid0 = tid * 2;
    #define COPY_STAGE(I, S)                                                        \
    {                                                                               \
        const int k0 = (I) * 32;                                                    \
        const uint32_t sb = sbase + (S) * STG_BYTES;                                \
        _Pragma("unroll")                                                           \
        for (int c = 0; c < 2; c++) {                                               \
            int id = aid0 + c;                                                      \
            int ar = id >> 2, ac = id & 3;                                          \
            const __nv_bfloat16* gA = Ahi + (size_t)(m0 + ar) * Dsz + k0 + ac * 8;  \
            const __nv_bfloat16* gAl = Alo + (size_t)(m0 + ar) * Dsz + k0 + ac * 8; \
            uint32_t dA = sb + ar * (A_STRIDE*2) + ac * 16;                         \
            cp16(dA, gA);                                                           \
            cp16(dA + A_BYTES, gAl);                                                \
            int br = id >> 4, bc = id & 15;                                         \
            const __nv_bfloat16* gB = Bhi + (size_t)(k0 + br) * Dsz + n0 + bc * 8;  \
            const __nv_bfloat16* gBl = Blo + (size_t)(k0 + br) * Dsz + n0 + bc * 8; \
            uint32_t dB = sb + 2*A_BYTES + br * (B_STRIDE*2) + bc * 16;             \
            cp16(dB, gB);                                                           \
            cp16(dB + B_BYTES, gBl);                                                \
        }                                                                           \
        asm volatile("cp.async.commit_group;");                                     \
    }

    COPY_STAGE(0, 0);
    COPY_STAGE(1, 1);

    for (int i = 0; i < 16; i++) {
        const int s = i % 3;
        if (i < 15) asm volatile("cp.async.wait_group 1;");
        else        asm volatile("cp.async.wait_group 0;");
        __syncthreads();

        const uint32_t sb   = sbase + s * STG_BYTES;
        const uint32_t sAhi = sb;
        const uint32_t sAlo = sb + A_BYTES;
        const uint32_t sBhi = sb + 2 * A_BYTES;
        const uint32_t sBlo = sBhi + B_BYTES;

        #pragma unroll
        for (int kk = 0; kk < 32; kk += 16) {
            unsigned ah[2][4], al[2][4];
            #pragma unroll
            for (int mt = 0; mt < 2; mt++) {
                uint32_t off = (uint32_t)(wm * 32 + mt * 16 + (lane & 15)) * (A_STRIDE*2)
                             + (kk + (lane >> 4) * 8) * 2;
                ldsm4(ah[mt], sAhi + off);
                ldsm4(al[mt], sAlo + off);
            }
            #pragma unroll
            for (int nn = 0; nn < 64; nn += 16) {
                unsigned bh[4], bl[4];
                uint32_t boff = (uint32_t)(kk + (lane & 15)) * (B_STRIDE*2)
                              + (wn * 64 + nn + (lane >> 4) * 8) * 2;
                ldsm4t(bh, sBhi + boff);
                ldsm4t(bl, sBlo + boff);
                #pragma unroll
                for (int mt = 0; mt < 2; mt++) {
                    #pragma unroll
                    for (int t = 0; t < 2; t++) {
                        mma_bf16(acc[mt][nn/8 + t], ah[mt], bh[2*t], bh[2*t+1]);
                        mma_bf16(acc[mt][nn/8 + t], al[mt], bh[2*t], bh[2*t+1]);
                        mma_bf16(acc[mt][nn/8 + t], ah[mt], bl[2*t], bl[2*t+1]);
                    }
                }
            }
        }
        // copy AFTER compute (proven order): overlaps with barrier/drain
        if (i + 2 < 16) { COPY_STAGE(i + 2, (i + 2) % 3); }
    }

    // epilogue
    #pragma unroll
    for (int mt = 0; mt < 2; mt++) {
        #pragma unroll
        for (int half = 0; half < 2; half++) {
            int m = m0 + wm * 32 + mt * 16 + (lane >> 2) + half * 8;
            if (m >= Mc) continue;
            int bos = (MODE == 0) ? g_rowbos[m] : 0;
            int gg = bos >> 8, sl = bos & 255;
            #pragma unroll
            for (int nt = 0; nt < 8; nt++) {
                int n = n0 + wn * 64 + nt * 8 + (lane & 3) * 2;
                float2 v;
                v.x = acc[mt][nt][half*2 + 0] + bias[n];
                v.y = acc[mt][nt][half*2 + 1] + bias[n + 1];
                if (MODE == 0) {
                    v.x *= scl; v.y *= scl;
                    unsigned hv = packbf(v.x, v.y);
                    float2 hb = __bfloat1622float2(*(__nv_bfloat162*)&hv);
                    unsigned lv = packbf(v.x - hb.x, v.y - hb.y);
                    int h = n >> 6, hd = n & 63;
                    size_t idx = (((size_t)(gg * Hsz + h) * Tsz + sl) * HDsz) + hd;
                    *(unsigned*)&Chi[idx] = hv;
                    *(unsigned*)&Clo[idx] = lv;
                } else {
                    *(float2*)&g_out[(size_t)m * Dsz + n] = v;
                }
            }
        }
    }
    #undef COPY_STAGE
}

// ---------------------------------------------------------------------------
// Tensor-core flash attention on compact slots. 1 CTA per (g,h), 8 warps.
// K/V double-buffered: loads for block kb+1 overlap compute of block kb.
// ---------------------------------------------------------------------------
#define QSTR 144
#define AQHI 0
#define AQLO (256*QSTR)                    // 36864
#define AKV0 (2*256*QSTR)                  // 73728
#define KVBUF (4*64*QSTR)                  // 36864 per buffer (Khi,Klo,Vhi,Vlo)
#define KOFF_HI 0
#define KOFF_LO (64*QSTR)
#define VOFF_HI (2*64*QSTR)
#define VOFF_LO (3*64*QSTR)
#define ATT_SMEM (AKV0 + 2*KVBUF)          // 147456

__global__ __launch_bounds__(256, 1)
void attn_k()
{
    extern __shared__ char sm[];
    const uint32_t sb = (uint32_t)__cvta_generic_to_shared(sm);

    const int blk = blockIdx.x;            // g*8 + h
    const int g = blk >> 3;
    const int h = blk & 7;
    const int nv = g_cnt[g];
    if (nv == 0) return;
    const int gstart = g_gstart[g];
    const int nkb = (nv + 63) >> 6;
    const int nq32 = (nv + 31) & ~31;      // Q rows actually needed (32-aligned)

    const int tid = threadIdx.x;
    const int lane = tid & 31;
    const int w = tid >> 5;
    const int c0 = (lane & 3) * 2;
    const bool wvalid = (w * 32 < nv);

    const size_t base = (size_t)blk * Tsz * HDsz;

    // KV stage issue (buffer bn, key block KB)
    #define KV_STAGE(KB, BN)                                                  \
    {                                                                         \
        const uint32_t kvb = sb + AKV0 + (BN) * KVBUF;                        \
        _Pragma("unroll")                                                     \
        for (int i = 0; i < 2; i++) {                                         \
            int id = tid + i * 256;                                           \
            int r = id >> 3, c = id & 7;                                      \
            int slot = (KB) * 64 + r;                                         \
            uint32_t d = r * QSTR + c * 16;                                   \
            if (slot < nv) {                                                  \
                size_t gb = base + (size_t)slot * 64 + c * 8;                 \
                cp16(kvb + KOFF_HI + d, g_khi + gb);                          \
                cp16(kvb + KOFF_LO + d, g_klo + gb);                          \
                cp16(kvb + VOFF_HI + d, g_vhi + gb);                          \
                cp16(kvb + VOFF_LO + d, g_vlo + gb);                          \
            } else {                                                          \
                st16z(kvb + KOFF_HI + d);                                     \
                st16z(kvb + KOFF_LO + d);                                     \
                st16z(kvb + VOFF_HI + d);                                     \
                st16z(kvb + VOFF_LO + d);                                     \
            }                                                                 \
        }                                                                     \
        asm volatile("cp.async.commit_group;");                               \
    }

    // prologue: Q (only needed rows) + KV(0) in one group
    #pragma unroll
    for (int i = 0; i < 8; i++) {
        int id = tid + i * 256;
        int r = id >> 3, c = id & 7;
        if (r < nq32) {
            cp16(sb + AQHI + r * QSTR + c * 16, g_qhi + base + (size_t)r * 64 + c * 8);
            cp16(sb + AQLO + r * QSTR + c * 16, g_qlo + base + (size_t)r * 64 + c * 8);
        }
    }
    KV_STAGE(0, 0);

    float O[2][8][4];
    #pragma unroll
    for (int a = 0; a < 2; a++)
        #pragma unroll
        for (int n = 0; n < 8; n++)
            #pragma unroll
            for (int c = 0; c < 4; c++) O[a][n][c] = 0.f;
    float mrow[2][2] = {{-1e30f, -1e30f}, {-1e30f, -1e30f}};
    float lrow[2][2] = {{0.f, 0.f}, {0.f, 0.f}};

    for (int kb = 0; kb < nkb; kb++) {
        __syncthreads();   // compute(kb-1) done everywhere: buffer (kb+1)&1 free
        if (kb + 1 < nkb) {
            KV_STAGE(kb + 1, (kb + 1) & 1);
            asm volatile("cp.async.wait_group 1;");   // waits group kb
        } else {
            asm volatile("cp.async.wait_group 0;");
        }
        __syncthreads();   // loads for kb visible to all

        if (!wvalid) continue;   // no barriers below within this iteration

        const uint32_t kvb = sb + AKV0 + (kb & 1) * KVBUF;

        float s[2][8][4];
        #pragma unroll
        for (int a = 0; a < 2; a++)
            #pragma unroll
            for (int n = 0; n < 8; n++)
                #pragma unroll
                for (int c = 0; c < 4; c++) s[a][n][c] = 0.f;

        #pragma unroll
        for (int kk = 0; kk < 64; kk += 16) {
            unsigned ah[2][4], al[2][4];
            #pragma unroll
            for (int mt = 0; mt < 2; mt++) {
                uint32_t aoff = (uint32_t)(w * 32 + mt * 16 + (lane & 15)) * QSTR
                              + (kk + (lane >> 4) * 8) * 2;
                ldsm4(ah[mt], sb + AQHI + aoff);
                ldsm4(al[mt], sb + AQLO + aoff);
            }
            #pragma unroll
            for (int nn = 0; nn < 64; nn += 16) {
                int row = nn + ((lane >> 4) << 3) + (lane & 7);
                int kc  = kk + (((lane >> 3) & 1) << 3);
                uint32_t boff = (uint32_t)row * QSTR + kc * 2;
                unsigned bh[4], bl[4];
                ldsm4(bh, kvb + KOFF_HI + boff);
                ldsm4(bl, kvb + KOFF_LO + boff);
                #pragma unroll
                for (int mt = 0; mt < 2; mt++) {
                    #pragma unroll
                    for (int t = 0; t < 2; t++) {
                        mma_bf16(s[mt][nn/8 + t], ah[mt], bh[2*t], bh[2*t+1]);
                        mma_bf16(s[mt][nn/8 + t], al[mt], bh[2*t], bh[2*t+1]);
                        mma_bf16(s[mt][nn/8 + t], ah[mt], bl[2*t], bl[2*t+1]);
                    }
                }
            }
        }

        // padded-slot bias + online softmax
        float nm[2][2] = {{mrow[0][0], mrow[0][1]}, {mrow[1][0], mrow[1][1]}};
        #pragma unroll
        for (int n8 = 0; n8 < 8; n8++) {
            int slot0 = kb * 64 + n8 * 8 + c0;
            float b0 = (slot0     < nv) ? 0.f : -1e30f;
            float b1 = (slot0 + 1 < nv) ? 0.f : -1e30f;
            #pragma unroll
            for (int mt = 0; mt < 2; mt++) {
                s[mt][n8][0] += b0; s[mt][n8][1] += b1;
                s[mt][n8][2] += b0; s[mt][n8][3] += b1;
                nm[mt][0] = fmaxf(nm[mt][0], fmaxf(s[mt][n8][0], s[mt][n8][1]));
                nm[mt][1] = fmaxf(nm[mt][1], fmaxf(s[mt][n8][2], s[mt][n8][3]));
            }
        }
        #pragma unroll
        for (int mt = 0; mt < 2; mt++)
            #pragma unroll
            for (int hf = 0; hf < 2; hf++) {
                float v = nm[mt][hf];
                v = fmaxf(v, __shfl_xor_sync(0xffffffffu, v, 1));
                v = fmaxf(v, __shfl_xor_sync(0xffffffffu, v, 2));
                nm[mt][hf] = v;
            }

        float rs[2][2] = {{0.f, 0.f}, {0.f, 0.f}};
        #pragma unroll
        for (int mt = 0; mt < 2; mt++)
            #pragma unroll
            for (int n8 = 0; n8 < 8; n8++) {
                float p0 = __expf(s[mt][n8][0] - nm[mt][0]);
                float p1 = __expf(s[mt][n8][1] - nm[mt][0]);
                float p2 = __expf(s[mt][n8][2] - nm[mt][1]);
                float p3 = __expf(s[mt][n8][3] - nm[mt][1]);
                s[mt][n8][0] = p0; s[mt][n8][1] = p1;
                s[mt][n8][2] = p2; s[mt][n8][3] = p3;
                rs[mt][0] += p0 + p1;
                rs[mt][1] += p2 + p3;
            }
        float alpha[2][2];
        #pragma unroll
        for (int mt = 0; mt < 2; mt++)
            #pragma unroll
            for (int hf = 0; hf < 2; hf++) {
                float v = rs[mt][hf];
                v += __shfl_xor_sync(0xffffffffu, v, 1);
                v += __shfl_xor_sync(0xffffffffu, v, 2);
                float al = __expf(mrow[mt][hf] - nm[mt][hf]);
                lrow[mt][hf] = lrow[mt][hf] * al + v;
                mrow[mt][hf] = nm[mt][hf];
                alpha[mt][hf] = al;
            }
        #pragma unroll
        for (int mt = 0; mt < 2; mt++)
            #pragma unroll
            for (int n8 = 0; n8 < 8; n8++) {
                O[mt][n8][0] *= alpha[mt][0]; O[mt][n8][1] *= alpha[mt][0];
                O[mt][n8][2] *= alpha[mt][1]; O[mt][n8][3] *= alpha[mt][1];
            }

        #pragma unroll
        for (int j = 0; j < 4; j++) {
            unsigned pa_hi[2][4], pa_lo[2][4];
            #pragma unroll
            for (int mt = 0; mt < 2; mt++) {
                #pragma unroll
                for (int q = 0; q < 2; q++) {
                    float p0 = s[mt][2*j + q][0], p1 = s[mt][2*j + q][1];
                    float p2 = s[mt][2*j + q][2], p3 = s[mt][2*j + q][3];
                    unsigned h0 = packbf(p0, p1);
                    unsigned h1 = packbf(p2, p3);
                    float2 f0 = __bfloat1622float2(*(__nv_bfloat162*)&h0);
                    float2 f1 = __bfloat1622float2(*(__nv_bfloat162*)&h1);
                    pa_hi[mt][2*q]   = h0;
                    pa_hi[mt][2*q+1] = h1;
                    pa_lo[mt][2*q]   = packbf(p0 - f0.x, p1 - f0.y);
                    pa_lo[mt][2*q+1] = packbf(p2 - f1.x, p3 - f1.y);
                }
            }
            #pragma unroll
            for (int nn = 0; nn < 64; nn += 16) {
                uint32_t boff = (uint32_t)(j * 16 + (lane & 15)) * QSTR
                              + (nn + (lane >> 4) * 8) * 2;
                unsigned vh[4], vl[4];
                ldsm4t(vh, kvb + VOFF_HI + boff);
                ldsm4t(vl, kvb + VOFF_LO + boff);
                #pragma unroll
                for (int mt = 0; mt < 2; mt++) {
                    #pragma unroll
                    for (int t = 0; t < 2; t++) {
                        mma_bf16(O[mt][nn/8 + t], pa_hi[mt], vh[2*t], vh[2*t+1]);
                        mma_bf16(O[mt][nn/8 + t], pa_lo[mt], vh[2*t], vh[2*t+1]);
                        mma_bf16(O[mt][nn/8 + t], pa_hi[mt], vl[2*t], vl[2*t+1]);
                    }
                }
            }
        }
    }
    #undef KV_STAGE

    if (!wvalid) return;

    float inv[2][2];
    #pragma unroll
    for (int mt = 0; mt < 2; mt++)
        #pragma unroll
        for (int hf = 0; hf < 2; hf++)
            inv[mt][hf] = (mrow[mt][hf] > -1e29f && lrow[mt][hf] > 0.f)
                        ? (1.f / lrow[mt][hf]) : 0.f;

    #pragma unroll
    for (int mt = 0; mt < 2; mt++) {
        #pragma unroll
        for (int hf = 0; hf < 2; hf++) {
            int slot = w * 32 + mt * 16 + (lane >> 2) + hf * 8;
            if (slot >= nv) continue;
            size_t orow = (size_t)(gstart + slot) * Dsz + (size_t)h * 64;
            #pragma unroll
            for (int n8 = 0; n8 < 8; n8++) {
                float v0 = O[mt][n8][hf*2 + 0] * inv[mt][hf];
                float v1 = O[mt][n8][hf*2 + 1] * inv[mt][hf];
                unsigned hv = packbf(v0, v1);
                float2 hb = __bfloat1622float2(*(__nv_bfloat162*)&hv);
                unsigned lv = packbf(v0 - hb.x, v1 - hb.y);
                size_t idx = orow + n8 * 8 + c0;
                *(unsigned*)&g_ahi[idx] = hv;
                *(unsigned*)&g_alo[idx] = lv;
            }
        }
    }
}

// ---------------------------------------------------------------------------
// LayerNorm, 2 rows per block (256 threads; half = row). Masked rows write
// zeros; valid rows gather compact g_out via g_rinv, normalize, write.
// All threads reach both barriers (no divergence hazard).
// ---------------------------------------------------------------------------
__global__ __launch_bounds__(256)
void ln_k(const float4* __restrict__ x,
          const float4* __restrict__ gamma,
          const float4* __restrict__ beta,
          float4* __restrict__ y)
{
    __shared__ float s1[2][4], s2[2][4];
    __shared__ float stats[2][2];

    const int half = threadIdx.x >> 7;           // 0/1: which row
    const int tid = threadIdx.x & 127;
    const int row = blockIdx.x * 2 + half;
    const size_t obase = (size_t)row * 128 + tid;

    const bool valid = (g_mask[row] != 0.f);
    float4 rr = make_float4(0.f, 0.f, 0.f, 0.f);
    if (valid) {
        const int r = g_rinv[row];
        float4 a = ((const float4*)g_out)[(size_t)r * 128 + tid];
        float4 xr = x[obase];
        rr.x = a.x + xr.x; rr.y = a.y + xr.y;
        rr.z = a.z + xr.z; rr.w = a.w + xr.w;
    }

    float s = rr.x + rr.y + rr.z + rr.w;
    float ss = rr.x * rr.x + rr.y * rr.y + rr.z * rr.z + rr.w * rr.w;
    #pragma unroll
    for (int off = 16; off > 0; off >>= 1) {
        s  += __shfl_down_sync(0xffffffffu, s, off);
        ss += __shfl_down_sync(0xffffffffu, ss, off);
    }
    if ((tid & 31) == 0) { s1[half][tid >> 5] = s; s2[half][tid >> 5] = ss; }
    __syncthreads();
    if (tid == 0) {
        float a2 = 0.f, b2 = 0.f;
        #pragma unroll
        for (int i = 0; i < 4; i++) { a2 += s1[half][i]; b2 += s2[half][i]; }
        stats[half][0] = a2; stats[half][1] = b2;
    }
    __syncthreads();

    if (!valid) {
        y[obase] = make_float4(0.f, 0.f, 0.f, 0.f);
        return;
    }

    float mean = stats[half][0] * (1.f / 512.f);
    float var  = stats[half][1] * (1.f / 512.f) - mean * mean;
    float rstd = rsqrtf(var + 1e-5f);

    float4 g = gamma[tid], bb = beta[tid];
    float4 out;
    out.x = (rr.x - mean) * rstd * g.x + bb.x;
    out.y = (rr.y - mean) * rstd * g.y + bb.y;
    out.z = (rr.z - mean) * rstd * g.z + bb.z;
    out.w = (rr.w - mean) * rstd * g.w + bb.w;
    y[obase] = out;
}

// ---------------------------------------------------------------------------
// Launch
// ---------------------------------------------------------------------------
extern "C" void kernel_launch(void* const* d_in, const int* in_sizes, int n_in,
                              void* d_out, int out_size)
{
    const float* x   = (const float*)d_in[0];
    const void* mask = d_in[1];
    const float* Wq = (const float*)d_in[2];
    const float* bq = (const float*)d_in[3];
    const float* Wk = (const float*)d_in[4];
    const float* bk = (const float*)d_in[5];
    const float* Wv = (const float*)d_in[6];
    const float* bv = (const float*)d_in[7];
    const float* Wo = (const float*)d_in[8];
    const float* bo = (const float*)d_in[9];
    const float* gamma = (const float*)d_in[10];
    const float* beta  = (const float*)d_in[11];
    float* y = (float*)d_out;

    cudaFuncSetAttribute(bgemm_k<0>, cudaFuncAttributeMaxDynamicSharedMemorySize, SMEM_TOTAL);
    cudaFuncSetAttribute(bgemm_k<3>, cudaFuncAttributeMaxDynamicSharedMemorySize, SMEM_TOTAL);
    cudaFuncSetAttribute(attn_k, cudaFuncAttributeMaxDynamicSharedMemorySize, ATT_SMEM);

    detect_k<<<NDET, 512>>>((const unsigned int*)mask);
    comp_scan_k<<<NGRP, 256>>>(mask);
    rowmap_k<<<NGRP, 256>>>();
    // fused X + W conversions, 4 float4/thread: 4096 X blocks + 256 W blocks
    conv_k<<<XBLKS + 256, 256>>>((const float4*)x,
                                 (const float4*)Wq, (const float4*)Wk,
                                 (const float4*)Wv, (const float4*)Wo);

    dim3 gqkv(Dsz / 128, Mrows / 128, 3);   // CTAs beyond Mc exit
    bgemm_k<0><<<gqkv, 256, SMEM_TOTAL>>>(bq, bk, bv);
    attn_k<<<NGRP * Hsz, 256, ATT_SMEM>>>();
    dim3 go(Dsz / 128, Mrows / 128);
    bgemm_k<3><<<go, 256, SMEM_TOTAL>>>(bo, bo, bo);
    ln_k<<<Mrows / 2, 256>>>((const float4*)x, (const float4*)gamma,
                             (const float4*)beta, (float4*)y);
}

// round 17
// speedup vs baseline: 1.0102x; 1.0102x over previous
#include <cuda_runtime.h>
#include <cuda_bf16.h>
#include <cstdint>

// Problem constants
#define Bsz  8
#define Tsz  256
#define Osz  16
#define Dsz  512
#define Hsz  8
#define HDsz 64
#define Mrows (Bsz*Tsz*Osz)      // 32768
#define ELEMS (Mrows*Dsz)        // 16777216
#define WSEG  (Dsz*Dsz)          // 262144
#define NGRP  (Bsz*Osz)          // 128
#define NDET  16

// ---------------------------------------------------------------------------
// Scratch (device globals: no allocation, graph-safe)
// ---------------------------------------------------------------------------
__device__ float g_out[ELEMS];                     // compact rows
__device__ float g_mask[Mrows];
__device__ int   g_bytespart[NDET];                // per-block detection partials
__device__ int   g_cnt[NGRP];
__device__ int   g_gstart[NGRP];
__device__ int   g_Mc;
__device__ int   g_tlist[NGRP*Tsz];
__device__ int   g_rowsrc[Mrows];                  // compact r -> X row index
__device__ int   g_rowbos[Mrows];                  // compact r -> (g<<8)|slot
__device__ int   g_rinv[Mrows];                    // X row -> compact r (valid rows only)
__device__ __align__(16) __nv_bfloat16 g_xhi[ELEMS];   // X split (COMPACT rows)
__device__ __align__(16) __nv_bfloat16 g_xlo[ELEMS];
__device__ __align__(16) __nv_bfloat16 g_ahi[ELEMS];   // att split (compact rows)
__device__ __align__(16) __nv_bfloat16 g_alo[ELEMS];
__device__ __align__(16) __nv_bfloat16 g_whi[4*WSEG];  // Wq,Wk,Wv,Wo split [k][n]
__device__ __align__(16) __nv_bfloat16 g_wlo[4*WSEG];
__device__ __align__(16) __nv_bfloat16 g_qhi[ELEMS];   // (g,h,slot,hd), pre-scaled
__device__ __align__(16) __nv_bfloat16 g_qlo[ELEMS];
__device__ __align__(16) __nv_bfloat16 g_khi[ELEMS];
__device__ __align__(16) __nv_bfloat16 g_klo[ELEMS];
__device__ __align__(16) __nv_bfloat16 g_vhi[ELEMS];
__device__ __align__(16) __nv_bfloat16 g_vlo[ELEMS];

// ---------------------------------------------------------------------------
// PTX helpers
// ---------------------------------------------------------------------------
__device__ __forceinline__ void cp16(uint32_t dst, const void* src) {
    asm volatile("cp.async.cg.shared.global [%0], [%1], 16;" :: "r"(dst), "l"(src));
}
__device__ __forceinline__ void st16z(uint32_t dst) {
    asm volatile("st.shared.v4.u32 [%0], {%1,%1,%1,%1};" :: "r"(dst), "r"(0u));
}
__device__ __forceinline__ void ldsm4(unsigned (&r)[4], uint32_t addr) {
    asm volatile("ldmatrix.sync.aligned.m8n8.x4.shared.b16 {%0,%1,%2,%3}, [%4];"
                 : "=r"(r[0]), "=r"(r[1]), "=r"(r[2]), "=r"(r[3]) : "r"(addr));
}
__device__ __forceinline__ void ldsm4t(unsigned (&r)[4], uint32_t addr) {
    asm volatile("ldmatrix.sync.aligned.m8n8.x4.trans.shared.b16 {%0,%1,%2,%3}, [%4];"
                 : "=r"(r[0]), "=r"(r[1]), "=r"(r[2]), "=r"(r[3]) : "r"(addr));
}
__device__ __forceinline__ void mma_bf16(float (&d)[4], const unsigned (&a)[4], unsigned b0, unsigned b1) {
    asm volatile("mma.sync.aligned.m16n8k16.row.col.f32.bf16.bf16.f32 "
                 "{%0,%1,%2,%3}, {%4,%5,%6,%7}, {%8,%9}, {%0,%1,%2,%3};"
                 : "+f"(d[0]), "+f"(d[1]), "+f"(d[2]), "+f"(d[3])
                 : "r"(a[0]), "r"(a[1]), "r"(a[2]), "r"(a[3]), "r"(b0), "r"(b1));
}
__device__ __forceinline__ unsigned packbf(float a, float b) {
    __nv_bfloat162 h = __floats2bfloat162_rn(a, b);
    return *(unsigned*)&h;
}

// ---------------------------------------------------------------------------
// Mask format detection over first 8192 int32 words (in-bounds for both
// possible marshalings; covers all bytes if byte-packed). Parallel, no atomics.
// ---------------------------------------------------------------------------
__global__ void detect_k(const unsigned int* __restrict__ mi)
{
    __shared__ int flag;
    if (threadIdx.x == 0) flag = 0;
    __syncthreads();
    int i = blockIdx.x * blockDim.x + threadIdx.x;   // 16 * 512 = 8192
    if (mi[i] > 1u) flag = 1;                        // benign race, same value
    __syncthreads();
    if (threadIdx.x == 0) g_bytespart[blockIdx.x] = flag;
}

// per-(b,o) compaction: normalize mask (writes g_mask) + counts + slot->t list
__global__ void comp_scan_k(const void* __restrict__ mraw)
{
    const int g = blockIdx.x, b = g >> 4, o = g & 15;
    const int tid = threadIdx.x, lane = tid & 31, w = tid >> 5;
    __shared__ int wtot[8];
    __shared__ int sbytes;
    if (tid < 32) {
        int f = (tid < NDET) ? g_bytespart[tid] : 0;
        #pragma unroll
        for (int off = 16; off > 0; off >>= 1) f |= __shfl_down_sync(0xffffffffu, f, off);
        if (tid == 0) sbytes = f;
    }
    __syncthreads();
    const bool bytes = (sbytes != 0);
    const size_t idx = (size_t)(b * Tsz + tid) * Osz + o;
    int v;
    if (bytes) v = ((const unsigned char*)mraw)[idx] ? 1 : 0;
    else       v = ((const unsigned int*)mraw)[idx] ? 1 : 0;
    g_mask[idx] = (float)v;

    unsigned bal = __ballot_sync(0xffffffffu, v);
    int pfx = __popc(bal & ((1u << lane) - 1u));
    if (lane == 31) wtot[w] = pfx + v;
    __syncthreads();
    int woff = 0;
    #pragma unroll
    for (int i = 0; i < 8; i++) woff += (i < w) ? wtot[i] : 0;
    if (v) g_tlist[g * Tsz + woff + pfx] = tid;
    if (tid == 255) g_cnt[g] = woff + pfx + v;
}

// compact row maps (forward + inverse) with fused per-block prefix over counts
__global__ void rowmap_k()
{
    __shared__ int scnt[NGRP];
    __shared__ int sgstart;
    const int g = blockIdx.x, s = threadIdx.x;
    if (s < NGRP) scnt[s] = g_cnt[s];
    __syncthreads();
    if (s == 0) {
        int acc = 0;
        for (int i = 0; i < g; i++) acc += scnt[i];
        sgstart = acc;
        g_gstart[g] = acc;
        if (g == NGRP - 1) g_Mc = acc + scnt[g];
    }
    __syncthreads();
    if (s < scnt[g]) {
        int t = g_tlist[g * Tsz + s];
        int r = sgstart + s;
        int xrow = (g >> 4) * (Tsz * Osz) + t * Osz + (g & 15);
        g_rowsrc[r] = xrow;
        g_rowbos[r] = (g << 8) | s;
        g_rinv[xrow] = r;
    }
}

// ---------------------------------------------------------------------------
// fp32 -> bf16 hi/lo split conversions
// ---------------------------------------------------------------------------
__device__ __forceinline__ void split4(float4 v, uint2& hi, uint2& lo) {
    __nv_bfloat162 h0 = __floats2bfloat162_rn(v.x, v.y);
    __nv_bfloat162 h1 = __floats2bfloat162_rn(v.z, v.w);
    float2 f0 = __bfloat1622float2(h0);
    float2 f1 = __bfloat1622float2(h1);
    __nv_bfloat162 l0 = __floats2bfloat162_rn(v.x - f0.x, v.y - f0.y);
    __nv_bfloat162 l1 = __floats2bfloat162_rn(v.z - f1.x, v.w - f1.y);
    hi.x = *(unsigned*)&h0; hi.y = *(unsigned*)&h1;
    lo.x = *(unsigned*)&l0; lo.y = *(unsigned*)&l1;
}

// fused conversions, 4 float4 per thread (MLP=4):
// blocks [0, 4096) = X gather-convert (compact rows),
// blocks [4096, 4352) = W split (4 matrices x 64 blocks).
#define XBLKS ((Mrows * 128) / 1024)    // 4096
__global__ void conv_k(const float4* __restrict__ x,
                       const float4* __restrict__ w0, const float4* __restrict__ w1,
                       const float4* __restrict__ w2, const float4* __restrict__ w3)
{
    const int blk = blockIdx.x;
    if (blk < XBLKS) {
        const int Mc = g_Mc;
        #pragma unroll
        for (int j = 0; j < 4; j++) {
            int i = blk * 1024 + j * 256 + threadIdx.x;   // compact float4 index
            int r = i >> 7;
            if (r >= Mc) continue;
            int xrow = g_rowsrc[r];
            uint2 hi, lo;
            split4(x[(size_t)xrow * 128 + (i & 127)], hi, lo);
            ((uint2*)g_xhi)[i] = hi;
            ((uint2*)g_xlo)[i] = lo;
        }
    } else {
        int wb = blk - XBLKS;                   // 0..255
        int mtx = wb >> 6;                      // 0..3
        const float4* src = (mtx == 0) ? w0 : (mtx == 1) ? w1 : (mtx == 2) ? w2 : w3;
        #pragma unroll
        for (int j = 0; j < 4; j++) {
            int i = (wb & 63) * 1024 + j * 256 + threadIdx.x; // 0..65535
            uint2 hi, lo;
            split4(src[i], hi, lo);
            size_t off = (size_t)mtx * (WSEG / 4) + i;
            ((uint2*)g_whi)[off] = hi;
            ((uint2*)g_wlo)[off] = lo;
        }
    }
}

// ---------------------------------------------------------------------------
// Tensor-core GEMM on COMPACT rows (split-bf16, 3-stage cp.async pipeline).
// MODE 0: fused QKV (blockIdx.z selects matrix); A = compact X splits,
//         C scattered to (g,h,slot) head-major bf16 hi/lo (Q scaled 0.125).
// MODE 3: A = compact att rows, C = compact g_out fp32.
// ---------------------------------------------------------------------------
#define A_STRIDE 40
#define B_STRIDE 136
#define A_BYTES  (128*A_STRIDE*2)          // 10240
#define B_BYTES  (32*B_STRIDE*2)           // 8704
#define STG_BYTES (2*A_BYTES + 2*B_BYTES)  // 37888
#define SMEM_TOTAL (3*STG_BYTES)           // 113664

template<int MODE>
__global__ __launch_bounds__(256, 2)
void bgemm_k(const float* __restrict__ bias0,
             const float* __restrict__ bias1,
             const float* __restrict__ bias2)
{
    const int Mc = g_Mc;
    const int m0 = blockIdx.y * 128;
    if (m0 >= Mc) return;

    const int z = (MODE == 0) ? blockIdx.z : 3;
    const __nv_bfloat16* Ahi = (MODE == 0) ? g_xhi : g_ahi;
    const __nv_bfloat16* Alo = (MODE == 0) ? g_xlo : g_alo;
    const __nv_bfloat16* Bhi = g_whi + (size_t)z * WSEG;
    const __nv_bfloat16* Blo = g_wlo + (size_t)z * WSEG;
    __nv_bfloat16* Chi = (z == 0) ? g_qhi : (z == 1) ? g_khi : g_vhi;
    __nv_bfloat16* Clo = (z == 0) ? g_qlo : (z == 1) ? g_klo : g_vlo;
    const float* bias = (MODE != 0) ? bias0 : (z == 0) ? bias0 : (z == 1) ? bias1 : bias2;
    const float scl = (MODE == 0 && z == 0) ? 0.125f : 1.f;

    extern __shared__ char smem[];
    const uint32_t sbase = (uint32_t)__cvta_generic_to_shared(smem);

    const int tid = threadIdx.x;
    const int lane = tid & 31;
    const int wid = tid >> 5;
    const int wm = wid & 3;
    const int wn = wid >> 2;
    const int n0 = blockIdx.x * 128;

    float acc[2][8][4];
    #pragma unroll
    for (int a = 0; a < 2; a++)
        #pragma unroll
        for (int b = 0; b < 8; b++)
            #pragma unroll
            for (int c = 0; c < 4; c++) acc[a][b][c] = 0.f;

    const int aid0 = tid * 2;
    #define COPY_STAGE(I, S)                                                        \
    {                                                                               \
        const int k0 = (I) * 32;                                                    \
        const uint32_t sb = sbase + (S) * STG_BYTES;                                \
        _Pragma("unroll")                                                           \
        for (int c = 0; c < 2; c++) {                                               \
            int id = aid0 + c;                                                      \
            int ar = id >> 2, ac = id & 3;                                          \
            const __nv_bfloat16* gA = Ahi + (size_t)(m0 + ar) * Dsz + k0 + ac * 8;  \
            const __nv_bfloat16* gAl = Alo + (size_t)(m0 + ar) * Dsz + k0 + ac * 8; \
            uint32_t dA = sb + ar * (A_STRIDE*2) + ac * 16;                         \
            cp16(dA, gA);                                                           \
            cp16(dA + A_BYTES, gAl);                                                \
            int br = id >> 4, bc = id & 15;                                         \
            const __nv_bfloat16* gB = Bhi + (size_t)(k0 + br) * Dsz + n0 + bc * 8;  \
            const __nv_bfloat16* gBl = Blo + (size_t)(k0 + br) * Dsz + n0 + bc * 8; \
            uint32_t dB = sb + 2*A_BYTES + br * (B_STRIDE*2) + bc * 16;             \
            cp16(dB, gB);                                                           \
            cp16(dB + B_BYTES, gBl);                                                \
        }                                                                           \
        asm volatile("cp.async.commit_group;");                                     \
    }

    COPY_STAGE(0, 0);
    COPY_STAGE(1, 1);

    for (int i = 0; i < 16; i++) {
        const int s = i % 3;
        if (i < 15) asm volatile("cp.async.wait_group 1;");
        else        asm volatile("cp.async.wait_group 0;");
        __syncthreads();

        const uint32_t sb   = sbase + s * STG_BYTES;
        const uint32_t sAhi = sb;
        const uint32_t sAlo = sb + A_BYTES;
        const uint32_t sBhi = sb + 2 * A_BYTES;
        const uint32_t sBlo = sBhi + B_BYTES;

        #pragma unroll
        for (int kk = 0; kk < 32; kk += 16) {
            unsigned ah[2][4], al[2][4];
            #pragma unroll
            for (int mt = 0; mt < 2; mt++) {
                uint32_t off = (uint32_t)(wm * 32 + mt * 16 + (lane & 15)) * (A_STRIDE*2)
                             + (kk + (lane >> 4) * 8) * 2;
                ldsm4(ah[mt], sAhi + off);
                ldsm4(al[mt], sAlo + off);
            }
            #pragma unroll
            for (int nn = 0; nn < 64; nn += 16) {
                unsigned bh[4], bl[4];
                uint32_t boff = (uint32_t)(kk + (lane & 15)) * (B_STRIDE*2)
                              + (wn * 64 + nn + (lane >> 4) * 8) * 2;
                ldsm4t(bh, sBhi + boff);
                ldsm4t(bl, sBlo + boff);
                #pragma unroll
                for (int mt = 0; mt < 2; mt++) {
                    #pragma unroll
                    for (int t = 0; t < 2; t++) {
                        mma_bf16(acc[mt][nn/8 + t], ah[mt], bh[2*t], bh[2*t+1]);
                        mma_bf16(acc[mt][nn/8 + t], al[mt], bh[2*t], bh[2*t+1]);
                        mma_bf16(acc[mt][nn/8 + t], ah[mt], bl[2*t], bl[2*t+1]);
                    }
                }
            }
        }
        // copy AFTER compute (proven order): overlaps with barrier/drain
        if (i + 2 < 16) { COPY_STAGE(i + 2, (i + 2) % 3); }
    }

    // epilogue
    #pragma unroll
    for (int mt = 0; mt < 2; mt++) {
        #pragma unroll
        for (int half = 0; half < 2; half++) {
            int m = m0 + wm * 32 + mt * 16 + (lane >> 2) + half * 8;
            if (m >= Mc) continue;
            int bos = (MODE == 0) ? g_rowbos[m] : 0;
            int gg = bos >> 8, sl = bos & 255;
            #pragma unroll
            for (int nt = 0; nt < 8; nt++) {
                int n = n0 + wn * 64 + nt * 8 + (lane & 3) * 2;
                float2 v;
                v.x = acc[mt][nt][half*2 + 0] + bias[n];
                v.y = acc[mt][nt][half*2 + 1] + bias[n + 1];
                if (MODE == 0) {
                    v.x *= scl; v.y *= scl;
                    unsigned hv = packbf(v.x, v.y);
                    float2 hb = __bfloat1622float2(*(__nv_bfloat162*)&hv);
                    unsigned lv = packbf(v.x - hb.x, v.y - hb.y);
                    int h = n >> 6, hd = n & 63;
                    size_t idx = (((size_t)(gg * Hsz + h) * Tsz + sl) * HDsz) + hd;
                    *(unsigned*)&Chi[idx] = hv;
                    *(unsigned*)&Clo[idx] = lv;
                } else {
                    *(float2*)&g_out[(size_t)m * Dsz + n] = v;
                }
            }
        }
    }
    #undef COPY_STAGE
}

// ---------------------------------------------------------------------------
// Tensor-core flash attention on compact slots. 1 CTA per (g,h), 8 warps.
// K/V double-buffered: loads for block kb+1 overlap compute of block kb.
// ---------------------------------------------------------------------------
#define QSTR 144
#define AQHI 0
#define AQLO (256*QSTR)                    // 36864
#define AKV0 (2*256*QSTR)                  // 73728
#define KVBUF (4*64*QSTR)                  // 36864 per buffer (Khi,Klo,Vhi,Vlo)
#define KOFF_HI 0
#define KOFF_LO (64*QSTR)
#define VOFF_HI (2*64*QSTR)
#define VOFF_LO (3*64*QSTR)
#define ATT_SMEM (AKV0 + 2*KVBUF)          // 147456

__global__ __launch_bounds__(256, 1)
void attn_k()
{
    extern __shared__ char sm[];
    const uint32_t sb = (uint32_t)__cvta_generic_to_shared(sm);

    const int blk = blockIdx.x;            // g*8 + h
    const int g = blk >> 3;
    const int h = blk & 7;
    const int nv = g_cnt[g];
    if (nv == 0) return;
    const int gstart = g_gstart[g];
    const int nkb = (nv + 63) >> 6;
    const int nq32 = (nv + 31) & ~31;      // Q rows actually needed (32-aligned)

    const int tid = threadIdx.x;
    const int lane = tid & 31;
    const int w = tid >> 5;
    const int c0 = (lane & 3) * 2;
    const bool wvalid = (w * 32 < nv);

    const size_t base = (size_t)blk * Tsz * HDsz;

    // KV stage issue (buffer bn, key block KB)
    #define KV_STAGE(KB, BN)                                                  \
    {                                                                         \
        const uint32_t kvb = sb + AKV0 + (BN) * KVBUF;                        \
        _Pragma("unroll")                                                     \
        for (int i = 0; i < 2; i++) {                                         \
            int id = tid + i * 256;                                           \
            int r = id >> 3, c = id & 7;                                      \
            int slot = (KB) * 64 + r;                                         \
            uint32_t d = r * QSTR + c * 16;                                   \
            if (slot < nv) {                                                  \
                size_t gb = base + (size_t)slot * 64 + c * 8;                 \
                cp16(kvb + KOFF_HI + d, g_khi + gb);                          \
                cp16(kvb + KOFF_LO + d, g_klo + gb);                          \
                cp16(kvb + VOFF_HI + d, g_vhi + gb);                          \
                cp16(kvb + VOFF_LO + d, g_vlo + gb);                          \
            } else {                                                          \
                st16z(kvb + KOFF_HI + d);                                     \
                st16z(kvb + KOFF_LO + d);                                     \
                st16z(kvb + VOFF_HI + d);                                     \
                st16z(kvb + VOFF_LO + d);                                     \
            }                                                                 \
        }                                                                     \
        asm volatile("cp.async.commit_group;");                               \
    }

    // prologue: Q (only needed rows) + KV(0) in one group
    #pragma unroll
    for (int i = 0; i < 8; i++) {
        int id = tid + i * 256;
        int r = id >> 3, c = id & 7;
        if (r < nq32) {
            cp16(sb + AQHI + r * QSTR + c * 16, g_qhi + base + (size_t)r * 64 + c * 8);
            cp16(sb + AQLO + r * QSTR + c * 16, g_qlo + base + (size_t)r * 64 + c * 8);
        }
    }
    KV_STAGE(0, 0);

    float O[2][8][4];
    #pragma unroll
    for (int a = 0; a < 2; a++)
        #pragma unroll
        for (int n = 0; n < 8; n++)
            #pragma unroll
            for (int c = 0; c < 4; c++) O[a][n][c] = 0.f;
    float mrow[2][2] = {{-1e30f, -1e30f}, {-1e30f, -1e30f}};
    float lrow[2][2] = {{0.f, 0.f}, {0.f, 0.f}};

    for (int kb = 0; kb < nkb; kb++) {
        __syncthreads();   // compute(kb-1) done everywhere: buffer (kb+1)&1 free
        if (kb + 1 < nkb) {
            KV_STAGE(kb + 1, (kb + 1) & 1);
            asm volatile("cp.async.wait_group 1;");   // waits group kb
        } else {
            asm volatile("cp.async.wait_group 0;");
        }
        __syncthreads();   // loads for kb visible to all

        if (!wvalid) continue;   // no barriers below within this iteration

        const uint32_t kvb = sb + AKV0 + (kb & 1) * KVBUF;

        float s[2][8][4];
        #pragma unroll
        for (int a = 0; a < 2; a++)
            #pragma unroll
            for (int n = 0; n < 8; n++)
                #pragma unroll
                for (int c = 0; c < 4; c++) s[a][n][c] = 0.f;

        #pragma unroll
        for (int kk = 0; kk < 64; kk += 16) {
            unsigned ah[2][4], al[2][4];
            #pragma unroll
            for (int mt = 0; mt < 2; mt++) {
                uint32_t aoff = (uint32_t)(w * 32 + mt * 16 + (lane & 15)) * QSTR
                              + (kk + (lane >> 4) * 8) * 2;
                ldsm4(ah[mt], sb + AQHI + aoff);
                ldsm4(al[mt], sb + AQLO + aoff);
            }
            #pragma unroll
            for (int nn = 0; nn < 64; nn += 16) {
                int row = nn + ((lane >> 4) << 3) + (lane & 7);
                int kc  = kk + (((lane >> 3) & 1) << 3);
                uint32_t boff = (uint32_t)row * QSTR + kc * 2;
                unsigned bh[4], bl[4];
                ldsm4(bh, kvb + KOFF_HI + boff);
                ldsm4(bl, kvb + KOFF_LO + boff);
                #pragma unroll
                for (int mt = 0; mt < 2; mt++) {
                    #pragma unroll
                    for (int t = 0; t < 2; t++) {
                        mma_bf16(s[mt][nn/8 + t], ah[mt], bh[2*t], bh[2*t+1]);
                        mma_bf16(s[mt][nn/8 + t], al[mt], bh[2*t], bh[2*t+1]);
                        mma_bf16(s[mt][nn/8 + t], ah[mt], bl[2*t], bl[2*t+1]);
                    }
                }
            }
        }

        // padded-slot bias + online softmax
        float nm[2][2] = {{mrow[0][0], mrow[0][1]}, {mrow[1][0], mrow[1][1]}};
        #pragma unroll
        for (int n8 = 0; n8 < 8; n8++) {
            int slot0 = kb * 64 + n8 * 8 + c0;
            float b0 = (slot0     < nv) ? 0.f : -1e30f;
            float b1 = (slot0 + 1 < nv) ? 0.f : -1e30f;
            #pragma unroll
            for (int mt = 0; mt < 2; mt++) {
                s[mt][n8][0] += b0; s[mt][n8][1] += b1;
                s[mt][n8][2] += b0; s[mt][n8][3] += b1;
                nm[mt][0] = fmaxf(nm[mt][0], fmaxf(s[mt][n8][0], s[mt][n8][1]));
                nm[mt][1] = fmaxf(nm[mt][1], fmaxf(s[mt][n8][2], s[mt][n8][3]));
            }
        }
        #pragma unroll
        for (int mt = 0; mt < 2; mt++)
            #pragma unroll
            for (int hf = 0; hf < 2; hf++) {
                float v = nm[mt][hf];
                v = fmaxf(v, __shfl_xor_sync(0xffffffffu, v, 1));
                v = fmaxf(v, __shfl_xor_sync(0xffffffffu, v, 2));
                nm[mt][hf] = v;
            }

        float rs[2][2] = {{0.f, 0.f}, {0.f, 0.f}};
        #pragma unroll
        for (int mt = 0; mt < 2; mt++)
            #pragma unroll
            for (int n8 = 0; n8 < 8; n8++) {
                float p0 = __expf(s[mt][n8][0] - nm[mt][0]);
                float p1 = __expf(s[mt][n8][1] - nm[mt][0]);
                float p2 = __expf(s[mt][n8][2] - nm[mt][1]);
                float p3 = __expf(s[mt][n8][3] - nm[mt][1]);
                s[mt][n8][0] = p0; s[mt][n8][1] = p1;
                s[mt][n8][2] = p2; s[mt][n8][3] = p3;
                rs[mt][0] += p0 + p1;
                rs[mt][1] += p2 + p3;
            }
        float alpha[2][2];
        #pragma unroll
        for (int mt = 0; mt < 2; mt++)
            #pragma unroll
            for (int hf = 0; hf < 2; hf++) {
                float v = rs[mt][hf];
                v += __shfl_xor_sync(0xffffffffu, v, 1);
                v += __shfl_xor_sync(0xffffffffu, v, 2);
                float al = __expf(mrow[mt][hf] - nm[mt][hf]);
                lrow[mt][hf] = lrow[mt][hf] * al + v;
                mrow[mt][hf] = nm[mt][hf];
                alpha[mt][hf] = al;
            }
        #pragma unroll
        for (int mt = 0; mt < 2; mt++)
            #pragma unroll
            for (int n8 = 0; n8 < 8; n8++) {
                O[mt][n8][0] *= alpha[mt][0]; O[mt][n8][1] *= alpha[mt][0];
                O[mt][n8][2] *= alpha[mt][1]; O[mt][n8][3] *= alpha[mt][1];
            }

        #pragma unroll
        for (int j = 0; j < 4; j++) {
            unsigned pa_hi[2][4], pa_lo[2][4];
            #pragma unroll
            for (int mt = 0; mt < 2; mt++) {
                #pragma unroll
                for (int q = 0; q < 2; q++) {
                    float p0 = s[mt][2*j + q][0], p1 = s[mt][2*j + q][1];
                    float p2 = s[mt][2*j + q][2], p3 = s[mt][2*j + q][3];
                    unsigned h0 = packbf(p0, p1);
                    unsigned h1 = packbf(p2, p3);
                    float2 f0 = __bfloat1622float2(*(__nv_bfloat162*)&h0);
                    float2 f1 = __bfloat1622float2(*(__nv_bfloat162*)&h1);
                    pa_hi[mt][2*q]   = h0;
                    pa_hi[mt][2*q+1] = h1;
                    pa_lo[mt][2*q]   = packbf(p0 - f0.x, p1 - f0.y);
                    pa_lo[mt][2*q+1] = packbf(p2 - f1.x, p3 - f1.y);
                }
            }
            #pragma unroll
            for (int nn = 0; nn < 64; nn += 16) {
                uint32_t boff = (uint32_t)(j * 16 + (lane & 15)) * QSTR
                              + (nn + (lane >> 4) * 8) * 2;
                unsigned vh[4], vl[4];
                ldsm4t(vh, kvb + VOFF_HI + boff);
                ldsm4t(vl, kvb + VOFF_LO + boff);
                #pragma unroll
                for (int mt = 0; mt < 2; mt++) {
                    #pragma unroll
                    for (int t = 0; t < 2; t++) {
                        mma_bf16(O[mt][nn/8 + t], pa_hi[mt], vh[2*t], vh[2*t+1]);
                        mma_bf16(O[mt][nn/8 + t], pa_lo[mt], vh[2*t], vh[2*t+1]);
                        mma_bf16(O[mt][nn/8 + t], pa_hi[mt], vl[2*t], vl[2*t+1]);
                    }
                }
            }
        }
    }
    #undef KV_STAGE

    if (!wvalid) return;

    float inv[2][2];
    #pragma unroll
    for (int mt = 0; mt < 2; mt++)
        #pragma unroll
        for (int hf = 0; hf < 2; hf++)
            inv[mt][hf] = (mrow[mt][hf] > -1e29f && lrow[mt][hf] > 0.f)
                        ? (1.f / lrow[mt][hf]) : 0.f;

    #pragma unroll
    for (int mt = 0; mt < 2; mt++) {
        #pragma unroll
        for (int hf = 0; hf < 2; hf++) {
            int slot = w * 32 + mt * 16 + (lane >> 2) + hf * 8;
            if (slot >= nv) continue;
            size_t orow = (size_t)(gstart + slot) * Dsz + (size_t)h * 64;
            #pragma unroll
            for (int n8 = 0; n8 < 8; n8++) {
                float v0 = O[mt][n8][hf*2 + 0] * inv[mt][hf];
                float v1 = O[mt][n8][hf*2 + 1] * inv[mt][hf];
                unsigned hv = packbf(v0, v1);
                float2 hb = __bfloat1622float2(*(__nv_bfloat162*)&hv);
                unsigned lv = packbf(v0 - hb.x, v1 - hb.y);
                size_t idx = orow + n8 * 8 + c0;
                *(unsigned*)&g_ahi[idx] = hv;
                *(unsigned*)&g_alo[idx] = lv;
            }
        }
    }
}

// ---------------------------------------------------------------------------
// LayerNorm over ALL rows: masked rows write zeros; valid rows gather
// compact g_out via g_rinv, normalize, write in place. (1 row / 128 thr)
// ---------------------------------------------------------------------------
__global__ __launch_bounds__(128)
void ln_k(const float4* __restrict__ x,
          const float4* __restrict__ gamma,
          const float4* __restrict__ beta,
          float4* __restrict__ y)
{
    __shared__ float s1[4], s2[4];
    __shared__ float stats[2];

    const int row = blockIdx.x;
    const int tid = threadIdx.x;
    const size_t obase = (size_t)row * 128 + tid;

    if (g_mask[row] == 0.f) {
        y[obase] = make_float4(0.f, 0.f, 0.f, 0.f);
        return;
    }
    const int r = g_rinv[row];

    float4 a = ((const float4*)g_out)[(size_t)r * 128 + tid];
    float4 xr = x[obase];
    float4 rr;
    rr.x = a.x + xr.x; rr.y = a.y + xr.y; rr.z = a.z + xr.z; rr.w = a.w + xr.w;

    float s = rr.x + rr.y + rr.z + rr.w;
    float ss = rr.x * rr.x + rr.y * rr.y + rr.z * rr.z + rr.w * rr.w;
    #pragma unroll
    for (int off = 16; off > 0; off >>= 1) {
        s  += __shfl_down_sync(0xffffffffu, s, off);
        ss += __shfl_down_sync(0xffffffffu, ss, off);
    }
    if ((tid & 31) == 0) { s1[tid >> 5] = s; s2[tid >> 5] = ss; }
    __syncthreads();
    if (tid == 0) {
        float a2 = 0.f, b2 = 0.f;
        #pragma unroll
        for (int i = 0; i < 4; i++) { a2 += s1[i]; b2 += s2[i]; }
        stats[0] = a2; stats[1] = b2;
    }
    __syncthreads();

    float mean = stats[0] * (1.f / 512.f);
    float var  = stats[1] * (1.f / 512.f) - mean * mean;
    float rstd = rsqrtf(var + 1e-5f);

    float4 g = gamma[tid], bb = beta[tid];
    float4 out;
    out.x = (rr.x - mean) * rstd * g.x + bb.x;
    out.y = (rr.y - mean) * rstd * g.y + bb.y;
    out.z = (rr.z - mean) * rstd * g.z + bb.z;
    out.w = (rr.w - mean) * rstd * g.w + bb.w;
    y[obase] = out;
}

// ---------------------------------------------------------------------------
// Launch
// ---------------------------------------------------------------------------
extern "C" void kernel_launch(void* const* d_in, const int* in_sizes, int n_in,
                              void* d_out, int out_size)
{
    const float* x   = (const float*)d_in[0];
    const void* mask = d_in[1];
    const float* Wq = (const float*)d_in[2];
    const float* bq = (const float*)d_in[3];
    const float* Wk = (const float*)d_in[4];
    const float* bk = (const float*)d_in[5];
    const float* Wv = (const float*)d_in[6];
    const float* bv = (const float*)d_in[7];
    const float* Wo = (const float*)d_in[8];
    const float* bo = (const float*)d_in[9];
    const float* gamma = (const float*)d_in[10];
    const float* beta  = (const float*)d_in[11];
    float* y = (float*)d_out;

    cudaFuncSetAttribute(bgemm_k<0>, cudaFuncAttributeMaxDynamicSharedMemorySize, SMEM_TOTAL);
    cudaFuncSetAttribute(bgemm_k<3>, cudaFuncAttributeMaxDynamicSharedMemorySize, SMEM_TOTAL);
    cudaFuncSetAttribute(attn_k, cudaFuncAttributeMaxDynamicSharedMemorySize, ATT_SMEM);

    detect_k<<<NDET, 512>>>((const unsigned int*)mask);
    comp_scan_k<<<NGRP, 256>>>(mask);
    rowmap_k<<<NGRP, 256>>>();
    // fused X + W conversions, 4 float4/thread: 4096 X blocks + 256 W blocks
    conv_k<<<XBLKS + 256, 256>>>((const float4*)x,
                                 (const float4*)Wq, (const float4*)Wk,
                                 (const float4*)Wv, (const float4*)Wo);

    dim3 gqkv(Dsz / 128, Mrows / 128, 3);   // CTAs beyond Mc exit
    bgemm_k<0><<<gqkv, 256, SMEM_TOTAL>>>(bq, bk, bv);
    attn_k<<<NGRP * Hsz, 256, ATT_SMEM>>>();
    dim3 go(Dsz / 128, Mrows / 128);
    bgemm_k<3><<<go, 256, SMEM_TOTAL>>>(bo, bo, bo);
    ln_k<<<Mrows, 128>>>((const float4*)x, (const float4*)gamma,
                         (const float4*)beta, (float4*)y);
}